// round 14
// baseline (speedup 1.0000x reference)
#include <cuda_runtime.h>
#include <cuda_bf16.h>
#include <math.h>
#include <stdint.h>

#define D 56
#define H 501
#define T 277
#define O 76
#define B 256
#define H3 1503
#define NBLK 128
#define NTHR 512
#define KPAD 512
#define MT_GATE 1108

typedef unsigned long long ull;
typedef uint32_t u32;
typedef __nv_bfloat16 bf16;

// ---- smem layout (bytes) ----
#define WSTRB 1040
#define WHI_OFF 0
#define WLO_OFF 49920
#define ASTRB 144                 /* 64 bf16 (128B) + 16 pad */
#define ABUF_HI 9216              /* 64 rows * 144 */
#define ABUF_SZ 18432             /* hi + lo */
#define ABUF_OFF 99840
#define AWG_STRIDE 36864          /* 2 bufs per warpgroup */
#define SMEM_BYTES (ABUF_OFF + 2 * AWG_STRIDE)   /* 173568 */

extern __shared__ char smc[];

// ---- static device scratch ----
__device__ float d_hin[B * D];
__device__ float d_g0[B * H3];
__device__ float d_gbuf[(long)T * B * H3];
__device__ bf16 d_yAhi[(long)T * B * KPAD], d_yAlo[(long)T * B * KPAD];
__device__ bf16 d_yBhi[(long)T * B * KPAD], d_yBlo[(long)T * B * KPAD];
__device__ bf16 d_whh[3][2][H3 * KPAD];
__device__ bf16 d_wih[2][2][H3 * KPAD];

// ---- grid barrier ----
__device__ unsigned int g_arrive = 0;
__device__ volatile unsigned int g_gen = 0;
__device__ __forceinline__ void grid_sync() {
    __syncthreads();
    if (threadIdx.x == 0) {
        __threadfence();
        unsigned int gen = g_gen;
        if (atomicAdd(&g_arrive, 1u) == (unsigned)(NBLK - 1)) {
            g_arrive = 0;
            __threadfence();
            g_gen = gen + 1;
        } else {
            while (g_gen == gen) { }
        }
        __threadfence();
    }
    __syncthreads();
}

// ---- PTX helpers ----
__device__ __forceinline__ u32 s2u(const void* p) {
    u32 a;
    asm("{ .reg .u64 t; cvta.to.shared.u64 t, %1; cvt.u32.u64 %0, t; }" : "=r"(a) : "l"(p));
    return a;
}
#define LDSM_X4(r0, r1, r2, r3, a) \
    asm volatile("ldmatrix.sync.aligned.m8n8.x4.shared.b16 {%0,%1,%2,%3}, [%4];" \
                 : "=r"(r0), "=r"(r1), "=r"(r2), "=r"(r3) : "r"(a))
#define LDSM_X2(r0, r1, a) \
    asm volatile("ldmatrix.sync.aligned.m8n8.x2.shared.b16 {%0,%1}, [%2];" \
                 : "=r"(r0), "=r"(r1) : "r"(a))
#define CP_ASYNC(sdst, gsrc) \
    asm volatile("cp.async.cg.shared.global [%0], [%1], 16;" :: "r"(sdst), "l"(gsrc))
#define CP_COMMIT() asm volatile("cp.async.commit_group;" ::: "memory")
#define CP_WAIT1() asm volatile("cp.async.wait_group 1;" ::: "memory")
#define CP_WAIT0() asm volatile("cp.async.wait_group 0;" ::: "memory")
#define BARWG(wg) asm volatile("bar.sync %0, 256;" :: "r"((wg) + 1) : "memory")

__device__ __forceinline__ void hmma(float c[4], const u32 a[4], u32 b0, u32 b1) {
    asm volatile(
        "mma.sync.aligned.m16n8k16.row.col.f32.bf16.bf16.f32 "
        "{%0,%1,%2,%3}, {%4,%5,%6,%7}, {%8,%9}, {%0,%1,%2,%3};"
        : "+f"(c[0]), "+f"(c[1]), "+f"(c[2]), "+f"(c[3])
        : "r"(a[0]), "r"(a[1]), "r"(a[2]), "r"(a[3]), "r"(b0), "r"(b1));
}

__device__ __forceinline__ float sigm(float x) { return 1.f / (1.f + __expf(-x)); }

// ---- weight hi/lo split precompute ----
__device__ void split_mat(const float* __restrict__ w, bf16* __restrict__ hi,
                          bf16* __restrict__ lo) {
    const long n = (long)H3 * KPAD;
    for (long i = (long)blockIdx.x * NTHR + threadIdx.x; i < n; i += (long)NBLK * NTHR) {
        const int r = (int)(i >> 9);
        const int k = (int)(i & (KPAD - 1));
        const float v = (k < H) ? w[(long)r * H + k] : 0.f;
        const bf16 h = __float2bfloat16(v);
        hi[i] = h;
        lo[i] = __float2bfloat16(v - __bfloat162float(h));
    }
}

// ---- load W hi+lo tile into smem ----
__device__ void load_W(const bf16* __restrict__ whi, const bf16* __restrict__ wlo, int n0) {
    for (int idx = threadIdx.x; idx < 3072; idx += NTHR) {
        const int r = idx >> 6;
        const int seg = idx & 63;
        const int g = r >> 4;
        const int n = n0 + (r & 15);
        uint4 vh = make_uint4(0, 0, 0, 0), vl = vh;
        if (n < H) {
            const long off = (long)(g * H + n) * KPAD + seg * 8;
            vh = *(const uint4*)(whi + off);
            vl = *(const uint4*)(wlo + off);
        }
        const u32 so = (u32)r * WSTRB + seg * 16;
        *(uint4*)(smc + WHI_OFF + so) = vh;
        *(uint4*)(smc + WLO_OFF + so) = vl;
    }
}

// ---- stage one 64x64 A chunk (hi+lo) for one warpgroup ----
__device__ __forceinline__ void stage_chunk(const bf16* __restrict__ ahi,
                                            const bf16* __restrict__ alo,
                                            int m0, int wg, int c, u32 sA, int wtid) {
#pragma unroll
    for (int i = 0; i < 2; i++) {
        const int idx = wtid + i * 256;
        const int row = idx >> 3;
        const int seg = idx & 7;
        const long go = (long)(m0 + row) * KPAD + wg * 256 + c * 64 + seg * 8;
        const u32 so = (u32)row * ASTRB + seg * 16;
        CP_ASYNC(sA + so, ahi + go);
        CP_ASYNC(sA + ABUF_HI + so, alo + go);
    }
}

// ---- 64x48x512 tile, split-K across 2 warpgroups, 3-term bf16 compensation ----
// cf valid in warpgroup 0 after return.
__device__ void run_tile(const bf16* __restrict__ ahi, const bf16* __restrict__ alo,
                         int m0, u32 sb, float cf[3][4]) {
    const int tid = threadIdx.x;
    const int wg = tid >> 8;
    const int wtid = tid & 255;
    const int w = wtid >> 5;
    const int mi = w >> 1;
    const int ns = w & 1;
    const int lane = tid & 31;

#pragma unroll
    for (int g = 0; g < 3; g++)
#pragma unroll
        for (int j = 0; j < 4; j++) cf[g][j] = 0.f;

    const u32 aoff = (u32)(mi * 16 + (lane & 15)) * ASTRB + (lane >> 4) * 16;
    const int gsel = lane >> 4;
    const int khalf = (lane >> 3) & 1;
    const u32 b01off = (u32)(gsel * 16 + ns * 8 + (lane & 7)) * WSTRB + khalf * 16;
    const int l2 = lane & 15;
    const u32 b2off = (u32)(32 + ns * 8 + (l2 & 7)) * WSTRB + (l2 >> 3) * 16;
    const u32 abase = sb + ABUF_OFF + wg * AWG_STRIDE;
    const u32 kwg = wg * 512;   // byte offset of this wg's k-range within a W row

    stage_chunk(ahi, alo, m0, wg, 0, abase, wtid);
    CP_COMMIT();

#pragma unroll 1
    for (int c = 0; c < 4; c++) {
        if (c < 3) {
            stage_chunk(ahi, alo, m0, wg, c + 1, abase + ((c + 1) & 1) * ABUF_SZ, wtid);
            CP_COMMIT();
            CP_WAIT1();
        } else {
            CP_WAIT0();
        }
        BARWG(wg);

        const u32 aH = abase + (c & 1) * ABUF_SZ + aoff;
        const u32 aL = aH + ABUF_HI;
        const u32 co = kwg + c * 128;
        const u32 bH01 = sb + WHI_OFF + b01off + co;
        const u32 bH2 = sb + WHI_OFF + b2off + co;
        const u32 bL01 = sb + WLO_OFF + b01off + co;
        const u32 bL2 = sb + WLO_OFF + b2off + co;

#pragma unroll
        for (int kk = 0; kk < 4; kk++) {
            const u32 ko = kk * 32;
            u32 ah[4], al[4], bh[4], bh2[2], bl[4], bl2[2];
            LDSM_X4(ah[0], ah[1], ah[2], ah[3], aH + ko);
            LDSM_X4(al[0], al[1], al[2], al[3], aL + ko);
            LDSM_X4(bh[0], bh[1], bh[2], bh[3], bH01 + ko);
            LDSM_X2(bh2[0], bh2[1], bH2 + ko);
            LDSM_X4(bl[0], bl[1], bl[2], bl[3], bL01 + ko);
            LDSM_X2(bl2[0], bl2[1], bL2 + ko);
            hmma(cf[0], ah, bh[0], bh[1]);
            hmma(cf[1], ah, bh[2], bh[3]);
            hmma(cf[2], ah, bh2[0], bh2[1]);
            hmma(cf[0], al, bh[0], bh[1]);
            hmma(cf[1], al, bh[2], bh[3]);
            hmma(cf[2], al, bh2[0], bh2[1]);
            hmma(cf[0], ah, bl[0], bl[1]);
            hmma(cf[1], ah, bl[2], bl[3]);
            hmma(cf[2], ah, bl2[0], bl2[1]);
        }
        BARWG(wg);
    }

    // cross-warpgroup reduction: wg1 -> smem -> wg0
    float* red = (float*)(smc + ABUF_OFF);
    __syncthreads();
    if (wg == 1) {
#pragma unroll
        for (int g = 0; g < 3; g++)
#pragma unroll
            for (int j = 0; j < 4; j++) red[wtid * 12 + g * 4 + j] = cf[g][j];
    }
    __syncthreads();
    if (wg == 0) {
#pragma unroll
        for (int g = 0; g < 3; g++)
#pragma unroll
            for (int j = 0; j < 4; j++) cf[g][j] += red[wtid * 12 + g * 4 + j];
    }
    __syncthreads();   // protect red area before next tile's staging
}

// ---- GRU layer scan: h carried in registers (warpgroup 0) ----
__device__ void scan_layer(const float* __restrict__ gsrc, long gstep,
                           const bf16* __restrict__ whi, const bf16* __restrict__ wlo,
                           const float* __restrict__ bhh,
                           bf16* __restrict__ yhi, bf16* __restrict__ ylo, u32 sb) {
    const int m0 = (blockIdx.x >> 5) * 64;
    const int n0 = (blockIdx.x & 31) * 16;
    const int tid = threadIdx.x;
    const bool wg0 = tid < 256;
    const int w = (tid & 255) >> 5;
    const int mi = w >> 1;
    const int ns = w & 1;
    const int lane = tid & 31;
    const int grp = lane >> 2;
    const int tig = lane & 3;

    load_W(whi, wlo, n0);
    __syncthreads();

    const int rows[2] = {m0 + mi * 16 + grp, m0 + mi * 16 + grp + 8};
    const int cols[2] = {n0 + ns * 8 + tig * 2, n0 + ns * 8 + tig * 2 + 1};
    const bool v[2] = {cols[0] < H, cols[1] < H};
    float br[2], bz[2], bn2[2];
#pragma unroll
    for (int j = 0; j < 2; j++) {
        br[j] = v[j] ? bhh[cols[j]] : 0.f;
        bz[j] = v[j] ? bhh[H + cols[j]] : 0.f;
        bn2[j] = v[j] ? bhh[2 * H + cols[j]] : 0.f;
    }
    float hreg[2][2] = {{0.f, 0.f}, {0.f, 0.f}};

    for (int t = 0; t < T; t++) {
        float ga[2][2][3];
        if (wg0) {
            const float* gp = gsrc + (long)t * gstep;
#pragma unroll
            for (int i = 0; i < 2; i++) {
                const float* gr = gp + (long)rows[i] * H3;
#pragma unroll
                for (int j = 0; j < 2; j++) {
                    ga[i][j][0] = v[j] ? gr[cols[j]] : 0.f;
                    ga[i][j][1] = v[j] ? gr[H + cols[j]] : 0.f;
                    ga[i][j][2] = v[j] ? gr[2 * H + cols[j]] : 0.f;
                }
            }
        }

        float cf[3][4];
        if (t > 0) {
            run_tile(yhi + (long)(t - 1) * B * KPAD, ylo + (long)(t - 1) * B * KPAD,
                     m0, sb, cf);
        } else {
#pragma unroll
            for (int g = 0; g < 3; g++)
#pragma unroll
                for (int j = 0; j < 4; j++) cf[g][j] = 0.f;
        }

        if (wg0) {
#pragma unroll
            for (int i = 0; i < 2; i++) {
                const long obase = ((long)t * B + rows[i]) * KPAD;
#pragma unroll
                for (int j = 0; j < 2; j++) {
                    float h = 0.f;
                    if (v[j]) {
                        const int reg = i * 2 + j;
                        const float r = sigm(ga[i][j][0] + cf[0][reg] + br[j]);
                        const float z = sigm(ga[i][j][1] + cf[1][reg] + bz[j]);
                        const float nn = tanhf(ga[i][j][2] + r * (cf[2][reg] + bn2[j]));
                        h = (1.f - z) * nn + z * hreg[i][j];
                    }
                    hreg[i][j] = h;
                    const bf16 hh = __float2bfloat16(h);
                    yhi[obase + cols[j]] = hh;
                    ylo[obase + cols[j]] = __float2bfloat16(h - __bfloat162float(hh));
                }
            }
        }
        grid_sync();
    }
}

// ---- batched input-gate GEMM ----
__device__ void gate_layer(const bf16* __restrict__ yhi, const bf16* __restrict__ ylo,
                           const bf16* __restrict__ whi, const bf16* __restrict__ wlo,
                           const float* __restrict__ bih, float* __restrict__ G, u32 sb) {
    const int n0 = (blockIdx.x & 31) * 16;
    const int mt0 = blockIdx.x >> 5;
    const int tid = threadIdx.x;
    const bool wg0 = tid < 256;
    const int w = (tid & 255) >> 5;
    const int mi = w >> 1;
    const int ns = w & 1;
    const int lane = tid & 31;
    const int grp = lane >> 2;
    const int tig = lane & 3;

    load_W(whi, wlo, n0);
    __syncthreads();

    const int cols[2] = {n0 + ns * 8 + tig * 2, n0 + ns * 8 + tig * 2 + 1};
    const bool v[2] = {cols[0] < H, cols[1] < H};
    float b0[2], b1[2], b2[2];
#pragma unroll
    for (int j = 0; j < 2; j++) {
        b0[j] = v[j] ? bih[cols[j]] : 0.f;
        b1[j] = v[j] ? bih[H + cols[j]] : 0.f;
        b2[j] = v[j] ? bih[2 * H + cols[j]] : 0.f;
    }

    for (int mt = mt0; mt < MT_GATE; mt += 4) {
        const int m0 = mt * 64;
        float cf[3][4];
        run_tile(yhi, ylo, m0, sb, cf);
        if (wg0) {
#pragma unroll
            for (int i = 0; i < 2; i++) {
                const long m = m0 + mi * 16 + grp + i * 8;
                float* gr = G + m * H3;
#pragma unroll
                for (int j = 0; j < 2; j++) {
                    if (v[j]) {
                        const int reg = i * 2 + j;
                        gr[cols[j]] = cf[0][reg] + b0[j];
                        gr[H + cols[j]] = cf[1][reg] + b1[j];
                        gr[2 * H + cols[j]] = cf[2][reg] + b2[j];
                    }
                }
            }
        }
    }
}

// ---- fc2 + permute to (B, O, T) ----
__device__ void fc2_phase(const bf16* __restrict__ yhi, const bf16* __restrict__ ylo,
                          const float* __restrict__ W, const float* __restrict__ bias,
                          float* __restrict__ out) {
    const int wid = threadIdx.x >> 5;   // 0..15
    const int lane = threadIdx.x & 31;
    const int M = T * B;
    float* rows = (float*)smc;          // 16 x 502 floats
    for (int base = blockIdx.x * 16; base < M; base += NBLK * 16) {
        const int row = base + wid;
        if (row < M) {
            for (int k = lane; k < H; k += 32)
                rows[wid * 502 + k] = __bfloat162float(yhi[(long)row * KPAD + k]) +
                                      __bfloat162float(ylo[(long)row * KPAD + k]);
            __syncwarp();
            const int t = row / B;
            const int b = row % B;
            for (int o = lane; o < O; o += 32) {
                float acc = bias[o];
                const float* wr = W + o * H;
                for (int k = 0; k < H; k++) acc += rows[wid * 502 + k] * wr[k];
                out[((long)b * O + o) * T + t] = acc;
            }
            __syncwarp();
        }
    }
}

// ---- persistent mega-kernel ----
__global__ void __launch_bounds__(NTHR, 1) decoder_kernel(
    const float* __restrict__ x,
    const float* __restrict__ fc1_w, const float* __restrict__ fc1_b,
    const float* __restrict__ w_ih0, const float* __restrict__ w_hh0,
    const float* __restrict__ b_ih0, const float* __restrict__ b_hh0,
    const float* __restrict__ w_ih1, const float* __restrict__ w_hh1,
    const float* __restrict__ b_ih1, const float* __restrict__ b_hh1,
    const float* __restrict__ w_ih2, const float* __restrict__ w_hh2,
    const float* __restrict__ b_ih2, const float* __restrict__ b_hh2,
    const float* __restrict__ fc2_w, const float* __restrict__ fc2_b,
    float* __restrict__ out) {
    const int tid = threadIdx.x;
    const u32 sb = s2u(smc);

    split_mat(w_hh0, d_whh[0][0], d_whh[0][1]);
    split_mat(w_hh1, d_whh[1][0], d_whh[1][1]);
    split_mat(w_hh2, d_whh[2][0], d_whh[2][1]);
    split_mat(w_ih1, d_wih[0][0], d_wih[0][1]);
    split_mat(w_ih2, d_wih[1][0], d_wih[1][1]);

    const int gt = blockIdx.x * NTHR + tid;
    const int GT = NBLK * NTHR;
    for (int i = gt; i < B * D; i += GT) {
        const int b = i / D, d = i % D;
        float acc = fc1_b[d];
        for (int k = 0; k < D; k++) acc += x[b * D + k] * fc1_w[d * D + k];
        d_hin[i] = fmaxf(acc, 0.f);
    }
    grid_sync();
    for (int i = gt; i < B * H3; i += GT) {
        const int b = i / H3, j = i % H3;
        float acc = b_ih0[j];
        for (int k = 0; k < D; k++) acc += d_hin[b * D + k] * w_ih0[j * D + k];
        d_g0[i] = acc;
    }
    grid_sync();

    scan_layer(d_g0, 0, d_whh[0][0], d_whh[0][1], b_hh0, d_yAhi, d_yAlo, sb);
    gate_layer(d_yAhi, d_yAlo, d_wih[0][0], d_wih[0][1], b_ih1, d_gbuf, sb);
    grid_sync();
    scan_layer(d_gbuf, (long)B * H3, d_whh[1][0], d_whh[1][1], b_hh1, d_yBhi, d_yBlo, sb);
    gate_layer(d_yBhi, d_yBlo, d_wih[1][0], d_wih[1][1], b_ih2, d_gbuf, sb);
    grid_sync();
    scan_layer(d_gbuf, (long)B * H3, d_whh[2][0], d_whh[2][1], b_hh2, d_yAhi, d_yAlo, sb);

    fc2_phase(d_yAhi, d_yAlo, fc2_w, fc2_b, out);
}

extern "C" void kernel_launch(void* const* d_in, const int* in_sizes, int n_in,
                              void* d_out, int out_size) {
    const float* x     = (const float*)d_in[0];
    const float* fc1_w = (const float*)d_in[1];
    const float* fc1_b = (const float*)d_in[2];
    const float* w_ih0 = (const float*)d_in[3];
    const float* w_hh0 = (const float*)d_in[4];
    const float* b_ih0 = (const float*)d_in[5];
    const float* b_hh0 = (const float*)d_in[6];
    const float* w_ih1 = (const float*)d_in[7];
    const float* w_hh1 = (const float*)d_in[8];
    const float* b_ih1 = (const float*)d_in[9];
    const float* b_hh1 = (const float*)d_in[10];
    const float* w_ih2 = (const float*)d_in[11];
    const float* w_hh2 = (const float*)d_in[12];
    const float* b_ih2 = (const float*)d_in[13];
    const float* b_hh2 = (const float*)d_in[14];
    const float* fc2_w = (const float*)d_in[15];
    const float* fc2_b = (const float*)d_in[16];
    float* out = (float*)d_out;

    cudaFuncSetAttribute(decoder_kernel, cudaFuncAttributeMaxDynamicSharedMemorySize,
                         SMEM_BYTES);
    decoder_kernel<<<NBLK, NTHR, SMEM_BYTES>>>(x, fc1_w, fc1_b,
                                               w_ih0, w_hh0, b_ih0, b_hh0,
                                               w_ih1, w_hh1, b_ih1, b_hh1,
                                               w_ih2, w_hh2, b_ih2, b_hh2,
                                               fc2_w, fc2_b, out);
}

// round 15
// speedup vs baseline: 1.0124x; 1.0124x over previous
#include <cuda_runtime.h>
#include <cuda_bf16.h>
#include <math.h>
#include <stdint.h>

#define D 56
#define H 501
#define T 277
#define O 76
#define B 256
#define H3 1503
#define NBLK 128
#define NTHR 512
#define KPAD 512
#define MT_GATE 1108

typedef unsigned long long ull;
typedef uint32_t u32;
typedef __nv_bfloat16 bf16;

// ---- smem layout (bytes) ----
#define WSTRB 1040
#define WHI_OFF 0
#define WLO_OFF 49920
#define ASTRB 144                 /* 64 bf16 (128B) + 16 pad */
#define ABUF_HI 9216              /* 64 rows * 144 */
#define ABUF_SZ 18432             /* hi + lo */
#define ABUF_OFF 99840
#define AWG_STRIDE 36864          /* 2 bufs per warpgroup */
#define SMEM_BYTES (ABUF_OFF + 2 * AWG_STRIDE)   /* 173568 */

extern __shared__ char smc[];

// ---- static device scratch ----
__device__ float d_hin[B * D];
__device__ float d_g0[B * H3];
__device__ float d_gbuf[(long)T * B * H3];
__device__ bf16 d_yAhi[(long)T * B * KPAD], d_yAlo[(long)T * B * KPAD];
__device__ bf16 d_yBhi[(long)T * B * KPAD], d_yBlo[(long)T * B * KPAD];
__device__ bf16 d_whh[3][2][H3 * KPAD];
__device__ bf16 d_wih[2][2][H3 * KPAD];

// ---- grid barrier ----
__device__ unsigned int g_arrive = 0;
__device__ volatile unsigned int g_gen = 0;
__device__ __forceinline__ void grid_sync() {
    __syncthreads();
    if (threadIdx.x == 0) {
        __threadfence();
        unsigned int gen = g_gen;
        if (atomicAdd(&g_arrive, 1u) == (unsigned)(NBLK - 1)) {
            g_arrive = 0;
            __threadfence();
            g_gen = gen + 1;
        } else {
            while (g_gen == gen) { }
        }
        __threadfence();
    }
    __syncthreads();
}

// ---- PTX helpers ----
__device__ __forceinline__ u32 s2u(const void* p) {
    u32 a;
    asm("{ .reg .u64 t; cvta.to.shared.u64 t, %1; cvt.u32.u64 %0, t; }" : "=r"(a) : "l"(p));
    return a;
}
#define LDSM_X4(r0, r1, r2, r3, a) \
    asm volatile("ldmatrix.sync.aligned.m8n8.x4.shared.b16 {%0,%1,%2,%3}, [%4];" \
                 : "=r"(r0), "=r"(r1), "=r"(r2), "=r"(r3) : "r"(a))
#define LDSM_X2(r0, r1, a) \
    asm volatile("ldmatrix.sync.aligned.m8n8.x2.shared.b16 {%0,%1}, [%2];" \
                 : "=r"(r0), "=r"(r1) : "r"(a))
#define CP_ASYNC(sdst, gsrc) \
    asm volatile("cp.async.cg.shared.global [%0], [%1], 16;" :: "r"(sdst), "l"(gsrc))
#define CP_COMMIT() asm volatile("cp.async.commit_group;" ::: "memory")
#define CP_WAIT1() asm volatile("cp.async.wait_group 1;" ::: "memory")
#define CP_WAIT0() asm volatile("cp.async.wait_group 0;" ::: "memory")
#define BARWG(wg) asm volatile("bar.sync %0, 256;" :: "r"((wg) + 1) : "memory")

__device__ __forceinline__ void hmma(float c[4], const u32 a[4], u32 b0, u32 b1) {
    asm volatile(
        "mma.sync.aligned.m16n8k16.row.col.f32.bf16.bf16.f32 "
        "{%0,%1,%2,%3}, {%4,%5,%6,%7}, {%8,%9}, {%0,%1,%2,%3};"
        : "+f"(c[0]), "+f"(c[1]), "+f"(c[2]), "+f"(c[3])
        : "r"(a[0]), "r"(a[1]), "r"(a[2]), "r"(a[3]), "r"(b0), "r"(b1));
}

__device__ __forceinline__ float sigm(float x) { return 1.f / (1.f + __expf(-x)); }

// ---- weight hi/lo split precompute ----
__device__ void split_mat(const float* __restrict__ w, bf16* __restrict__ hi,
                          bf16* __restrict__ lo) {
    const long n = (long)H3 * KPAD;
    for (long i = (long)blockIdx.x * NTHR + threadIdx.x; i < n; i += (long)NBLK * NTHR) {
        const int r = (int)(i >> 9);
        const int k = (int)(i & (KPAD - 1));
        const float v = (k < H) ? w[(long)r * H + k] : 0.f;
        const bf16 h = __float2bfloat16(v);
        hi[i] = h;
        lo[i] = __float2bfloat16(v - __bfloat162float(h));
    }
}

// ---- load W hi+lo tile into smem ----
__device__ void load_W(const bf16* __restrict__ whi, const bf16* __restrict__ wlo, int n0) {
    for (int idx = threadIdx.x; idx < 3072; idx += NTHR) {
        const int r = idx >> 6;
        const int seg = idx & 63;
        const int g = r >> 4;
        const int n = n0 + (r & 15);
        uint4 vh = make_uint4(0, 0, 0, 0), vl = vh;
        if (n < H) {
            const long off = (long)(g * H + n) * KPAD + seg * 8;
            vh = *(const uint4*)(whi + off);
            vl = *(const uint4*)(wlo + off);
        }
        const u32 so = (u32)r * WSTRB + seg * 16;
        *(uint4*)(smc + WHI_OFF + so) = vh;
        *(uint4*)(smc + WLO_OFF + so) = vl;
    }
}

// ---- stage one 64x64 A chunk (hi+lo) for one warpgroup ----
__device__ __forceinline__ void stage_chunk(const bf16* __restrict__ ahi,
                                            const bf16* __restrict__ alo,
                                            int m0, int wg, int c, u32 sA, int wtid) {
#pragma unroll
    for (int i = 0; i < 2; i++) {
        const int idx = wtid + i * 256;
        const int row = idx >> 3;
        const int seg = idx & 7;
        const long go = (long)(m0 + row) * KPAD + wg * 256 + c * 64 + seg * 8;
        const u32 so = (u32)row * ASTRB + seg * 16;
        CP_ASYNC(sA + so, ahi + go);
        CP_ASYNC(sA + ABUF_HI + so, alo + go);
    }
}

// ---- 64x48x512 tile, split-K across 2 warpgroups, 3-term bf16 compensation ----
// cf valid in warpgroup 0 after return.
__device__ void run_tile(const bf16* __restrict__ ahi, const bf16* __restrict__ alo,
                         int m0, u32 sb, float cf[3][4]) {
    const int tid = threadIdx.x;
    const int wg = tid >> 8;
    const int wtid = tid & 255;
    const int w = wtid >> 5;
    const int mi = w >> 1;
    const int ns = w & 1;
    const int lane = tid & 31;

#pragma unroll
    for (int g = 0; g < 3; g++)
#pragma unroll
        for (int j = 0; j < 4; j++) cf[g][j] = 0.f;

    const u32 aoff = (u32)(mi * 16 + (lane & 15)) * ASTRB + (lane >> 4) * 16;
    const int gsel = lane >> 4;
    const int khalf = (lane >> 3) & 1;
    const u32 b01off = (u32)(gsel * 16 + ns * 8 + (lane & 7)) * WSTRB + khalf * 16;
    const int l2 = lane & 15;
    const u32 b2off = (u32)(32 + ns * 8 + (l2 & 7)) * WSTRB + (l2 >> 3) * 16;
    const u32 abase = sb + ABUF_OFF + wg * AWG_STRIDE;
    const u32 kwg = wg * 512;   // byte offset of this wg's k-range within a W row

    stage_chunk(ahi, alo, m0, wg, 0, abase, wtid);
    CP_COMMIT();

#pragma unroll 1
    for (int c = 0; c < 4; c++) {
        if (c < 3) {
            stage_chunk(ahi, alo, m0, wg, c + 1, abase + ((c + 1) & 1) * ABUF_SZ, wtid);
            CP_COMMIT();
            CP_WAIT1();
        } else {
            CP_WAIT0();
        }
        BARWG(wg);

        const u32 aH = abase + (c & 1) * ABUF_SZ + aoff;
        const u32 aL = aH + ABUF_HI;
        const u32 co = kwg + c * 128;
        const u32 bH01 = sb + WHI_OFF + b01off + co;
        const u32 bH2 = sb + WHI_OFF + b2off + co;
        const u32 bL01 = sb + WLO_OFF + b01off + co;
        const u32 bL2 = sb + WLO_OFF + b2off + co;

#pragma unroll
        for (int kk = 0; kk < 4; kk++) {
            const u32 ko = kk * 32;
            u32 ah[4], al[4], bh[4], bh2[2], bl[4], bl2[2];
            LDSM_X4(ah[0], ah[1], ah[2], ah[3], aH + ko);
            LDSM_X4(al[0], al[1], al[2], al[3], aL + ko);
            LDSM_X4(bh[0], bh[1], bh[2], bh[3], bH01 + ko);
            LDSM_X2(bh2[0], bh2[1], bH2 + ko);
            LDSM_X4(bl[0], bl[1], bl[2], bl[3], bL01 + ko);
            LDSM_X2(bl2[0], bl2[1], bL2 + ko);
            hmma(cf[0], ah, bh[0], bh[1]);
            hmma(cf[1], ah, bh[2], bh[3]);
            hmma(cf[2], ah, bh2[0], bh2[1]);
            hmma(cf[0], al, bh[0], bh[1]);
            hmma(cf[1], al, bh[2], bh[3]);
            hmma(cf[2], al, bh2[0], bh2[1]);
            hmma(cf[0], ah, bl[0], bl[1]);
            hmma(cf[1], ah, bl[2], bl[3]);
            hmma(cf[2], ah, bl2[0], bl2[1]);
        }
        BARWG(wg);
    }

    // cross-warpgroup reduction: wg1 -> smem -> wg0
    float* red = (float*)(smc + ABUF_OFF);
    __syncthreads();
    if (wg == 1) {
#pragma unroll
        for (int g = 0; g < 3; g++)
#pragma unroll
            for (int j = 0; j < 4; j++) red[wtid * 12 + g * 4 + j] = cf[g][j];
    }
    __syncthreads();
    if (wg == 0) {
#pragma unroll
        for (int g = 0; g < 3; g++)
#pragma unroll
            for (int j = 0; j < 4; j++) cf[g][j] += red[wtid * 12 + g * 4 + j];
    }
    __syncthreads();   // protect red area before next tile's staging
}

// ---- GRU layer scan: h carried in registers (warpgroup 0) ----
__device__ void scan_layer(const float* __restrict__ gsrc, long gstep,
                           const bf16* __restrict__ whi, const bf16* __restrict__ wlo,
                           const float* __restrict__ bhh,
                           bf16* __restrict__ yhi, bf16* __restrict__ ylo, u32 sb) {
    const int m0 = (blockIdx.x >> 5) * 64;
    const int n0 = (blockIdx.x & 31) * 16;
    const int tid = threadIdx.x;
    const bool wg0 = tid < 256;
    const int w = (tid & 255) >> 5;
    const int mi = w >> 1;
    const int ns = w & 1;
    const int lane = tid & 31;
    const int grp = lane >> 2;
    const int tig = lane & 3;

    load_W(whi, wlo, n0);
    __syncthreads();

    const int rows[2] = {m0 + mi * 16 + grp, m0 + mi * 16 + grp + 8};
    const int cols[2] = {n0 + ns * 8 + tig * 2, n0 + ns * 8 + tig * 2 + 1};
    const bool v[2] = {cols[0] < H, cols[1] < H};
    float br[2], bz[2], bn2[2];
#pragma unroll
    for (int j = 0; j < 2; j++) {
        br[j] = v[j] ? bhh[cols[j]] : 0.f;
        bz[j] = v[j] ? bhh[H + cols[j]] : 0.f;
        bn2[j] = v[j] ? bhh[2 * H + cols[j]] : 0.f;
    }
    float hreg[2][2] = {{0.f, 0.f}, {0.f, 0.f}};

    for (int t = 0; t < T; t++) {
        float ga[2][2][3];
        if (wg0) {
            const float* gp = gsrc + (long)t * gstep;
#pragma unroll
            for (int i = 0; i < 2; i++) {
                const float* gr = gp + (long)rows[i] * H3;
#pragma unroll
                for (int j = 0; j < 2; j++) {
                    ga[i][j][0] = v[j] ? gr[cols[j]] : 0.f;
                    ga[i][j][1] = v[j] ? gr[H + cols[j]] : 0.f;
                    ga[i][j][2] = v[j] ? gr[2 * H + cols[j]] : 0.f;
                }
            }
        }

        float cf[3][4];
        if (t > 0) {
            run_tile(yhi + (long)(t - 1) * B * KPAD, ylo + (long)(t - 1) * B * KPAD,
                     m0, sb, cf);
        } else {
#pragma unroll
            for (int g = 0; g < 3; g++)
#pragma unroll
                for (int j = 0; j < 4; j++) cf[g][j] = 0.f;
        }

        if (wg0) {
#pragma unroll
            for (int i = 0; i < 2; i++) {
                const long obase = ((long)t * B + rows[i]) * KPAD;
#pragma unroll
                for (int j = 0; j < 2; j++) {
                    float h = 0.f;
                    if (v[j]) {
                        const int reg = i * 2 + j;
                        const float r = sigm(ga[i][j][0] + cf[0][reg] + br[j]);
                        const float z = sigm(ga[i][j][1] + cf[1][reg] + bz[j]);
                        const float nn = tanhf(ga[i][j][2] + r * (cf[2][reg] + bn2[j]));
                        h = (1.f - z) * nn + z * hreg[i][j];
                    }
                    hreg[i][j] = h;
                    const bf16 hh = __float2bfloat16(h);
                    yhi[obase + cols[j]] = hh;
                    ylo[obase + cols[j]] = __float2bfloat16(h - __bfloat162float(hh));
                }
            }
        }
        grid_sync();
    }
}

// ---- batched input-gate GEMM ----
__device__ void gate_layer(const bf16* __restrict__ yhi, const bf16* __restrict__ ylo,
                           const bf16* __restrict__ whi, const bf16* __restrict__ wlo,
                           const float* __restrict__ bih, float* __restrict__ G, u32 sb) {
    const int n0 = (blockIdx.x & 31) * 16;
    const int mt0 = blockIdx.x >> 5;
    const int tid = threadIdx.x;
    const bool wg0 = tid < 256;
    const int w = (tid & 255) >> 5;
    const int mi = w >> 1;
    const int ns = w & 1;
    const int lane = tid & 31;
    const int grp = lane >> 2;
    const int tig = lane & 3;

    load_W(whi, wlo, n0);
    __syncthreads();

    const int cols[2] = {n0 + ns * 8 + tig * 2, n0 + ns * 8 + tig * 2 + 1};
    const bool v[2] = {cols[0] < H, cols[1] < H};
    float b0[2], b1[2], b2[2];
#pragma unroll
    for (int j = 0; j < 2; j++) {
        b0[j] = v[j] ? bih[cols[j]] : 0.f;
        b1[j] = v[j] ? bih[H + cols[j]] : 0.f;
        b2[j] = v[j] ? bih[2 * H + cols[j]] : 0.f;
    }

    for (int mt = mt0; mt < MT_GATE; mt += 4) {
        const int m0 = mt * 64;
        float cf[3][4];
        run_tile(yhi, ylo, m0, sb, cf);
        if (wg0) {
#pragma unroll
            for (int i = 0; i < 2; i++) {
                const long m = m0 + mi * 16 + grp + i * 8;
                float* gr = G + m * H3;
#pragma unroll
                for (int j = 0; j < 2; j++) {
                    if (v[j]) {
                        const int reg = i * 2 + j;
                        gr[cols[j]] = cf[0][reg] + b0[j];
                        gr[H + cols[j]] = cf[1][reg] + b1[j];
                        gr[2 * H + cols[j]] = cf[2][reg] + b2[j];
                    }
                }
            }
        }
    }
}

// ---- fc2 + permute to (B, O, T) ----
__device__ void fc2_phase(const bf16* __restrict__ yhi, const bf16* __restrict__ ylo,
                          const float* __restrict__ W, const float* __restrict__ bias,
                          float* __restrict__ out) {
    const int wid = threadIdx.x >> 5;   // 0..15
    const int lane = threadIdx.x & 31;
    const int M = T * B;
    float* rows = (float*)smc;          // 16 x 502 floats
    for (int base = blockIdx.x * 16; base < M; base += NBLK * 16) {
        const int row = base + wid;
        if (row < M) {
            for (int k = lane; k < H; k += 32)
                rows[wid * 502 + k] = __bfloat162float(yhi[(long)row * KPAD + k]) +
                                      __bfloat162float(ylo[(long)row * KPAD + k]);
            __syncwarp();
            const int t = row / B;
            const int b = row % B;
            for (int o = lane; o < O; o += 32) {
                float acc = bias[o];
                const float* wr = W + o * H;
                for (int k = 0; k < H; k++) acc += rows[wid * 502 + k] * wr[k];
                out[((long)b * O + o) * T + t] = acc;
            }
            __syncwarp();
        }
    }
}

// ---- persistent mega-kernel ----
__global__ void __launch_bounds__(NTHR, 1) decoder_kernel(
    const float* __restrict__ x,
    const float* __restrict__ fc1_w, const float* __restrict__ fc1_b,
    const float* __restrict__ w_ih0, const float* __restrict__ w_hh0,
    const float* __restrict__ b_ih0, const float* __restrict__ b_hh0,
    const float* __restrict__ w_ih1, const float* __restrict__ w_hh1,
    const float* __restrict__ b_ih1, const float* __restrict__ b_hh1,
    const float* __restrict__ w_ih2, const float* __restrict__ w_hh2,
    const float* __restrict__ b_ih2, const float* __restrict__ b_hh2,
    const float* __restrict__ fc2_w, const float* __restrict__ fc2_b,
    float* __restrict__ out) {
    const int tid = threadIdx.x;
    const u32 sb = s2u(smc);

    split_mat(w_hh0, d_whh[0][0], d_whh[0][1]);
    split_mat(w_hh1, d_whh[1][0], d_whh[1][1]);
    split_mat(w_hh2, d_whh[2][0], d_whh[2][1]);
    split_mat(w_ih1, d_wih[0][0], d_wih[0][1]);
    split_mat(w_ih2, d_wih[1][0], d_wih[1][1]);

    const int gt = blockIdx.x * NTHR + tid;
    const int GT = NBLK * NTHR;
    for (int i = gt; i < B * D; i += GT) {
        const int b = i / D, d = i % D;
        float acc = fc1_b[d];
        for (int k = 0; k < D; k++) acc += x[b * D + k] * fc1_w[d * D + k];
        d_hin[i] = fmaxf(acc, 0.f);
    }
    grid_sync();
    for (int i = gt; i < B * H3; i += GT) {
        const int b = i / H3, j = i % H3;
        float acc = b_ih0[j];
        for (int k = 0; k < D; k++) acc += d_hin[b * D + k] * w_ih0[j * D + k];
        d_g0[i] = acc;
    }
    grid_sync();

    scan_layer(d_g0, 0, d_whh[0][0], d_whh[0][1], b_hh0, d_yAhi, d_yAlo, sb);
    gate_layer(d_yAhi, d_yAlo, d_wih[0][0], d_wih[0][1], b_ih1, d_gbuf, sb);
    grid_sync();
    scan_layer(d_gbuf, (long)B * H3, d_whh[1][0], d_whh[1][1], b_hh1, d_yBhi, d_yBlo, sb);
    gate_layer(d_yBhi, d_yBlo, d_wih[1][0], d_wih[1][1], b_ih2, d_gbuf, sb);
    grid_sync();
    scan_layer(d_gbuf, (long)B * H3, d_whh[2][0], d_whh[2][1], b_hh2, d_yAhi, d_yAlo, sb);

    fc2_phase(d_yAhi, d_yAlo, fc2_w, fc2_b, out);
}

extern "C" void kernel_launch(void* const* d_in, const int* in_sizes, int n_in,
                              void* d_out, int out_size) {
    const float* x     = (const float*)d_in[0];
    const float* fc1_w = (const float*)d_in[1];
    const float* fc1_b = (const float*)d_in[2];
    const float* w_ih0 = (const float*)d_in[3];
    const float* w_hh0 = (const float*)d_in[4];
    const float* b_ih0 = (const float*)d_in[5];
    const float* b_hh0 = (const float*)d_in[6];
    const float* w_ih1 = (const float*)d_in[7];
    const float* w_hh1 = (const float*)d_in[8];
    const float* b_ih1 = (const float*)d_in[9];
    const float* b_hh1 = (const float*)d_in[10];
    const float* w_ih2 = (const float*)d_in[11];
    const float* w_hh2 = (const float*)d_in[12];
    const float* b_ih2 = (const float*)d_in[13];
    const float* b_hh2 = (const float*)d_in[14];
    const float* fc2_w = (const float*)d_in[15];
    const float* fc2_b = (const float*)d_in[16];
    float* out = (float*)d_out;

    cudaFuncSetAttribute(decoder_kernel, cudaFuncAttributeMaxDynamicSharedMemorySize,
                         SMEM_BYTES);
    decoder_kernel<<<NBLK, NTHR, SMEM_BYTES>>>(x, fc1_w, fc1_b,
                                               w_ih0, w_hh0, b_ih0, b_hh0,
                                               w_ih1, w_hh1, b_ih1, b_hh1,
                                               w_ih2, w_hh2, b_ih2, b_hh2,
                                               fc2_w, fc2_b, out);
}

// round 16
// speedup vs baseline: 1.0206x; 1.0080x over previous
#include <cuda_runtime.h>
#include <cuda_bf16.h>
#include <math.h>
#include <stdint.h>

#define D 56
#define H 501
#define T 277
#define O 76
#define B 256
#define H3 1503
#define NBLK 128
#define NTHR 512
#define KPAD 512
#define MT_GATE 1108

typedef unsigned long long ull;
typedef uint32_t u32;
typedef __nv_bfloat16 bf16;

// ---- smem layout (bytes) ----
#define WSTRB 1040
#define WHI_OFF 0
#define WLO_OFF 49920
#define ASTRB 144                 /* 64 bf16 (128B) + 16 pad */
#define ABUF_HI 9216              /* 64 rows * 144 */
#define ABUF_SZ 18432             /* hi + lo */
#define ABUF_OFF 99840
#define AWG_STRIDE 36864          /* 2 bufs per warpgroup */
#define SMEM_BYTES (ABUF_OFF + 2 * AWG_STRIDE)   /* 173568 */

extern __shared__ char smc[];

// ---- static device scratch ----
__device__ float d_hin[B * D];
__device__ float d_g0[B * H3];
__device__ float d_gbuf[(long)T * B * H3];
__device__ bf16 d_yAhi[(long)T * B * KPAD], d_yAlo[(long)T * B * KPAD];
__device__ bf16 d_yBhi[(long)T * B * KPAD], d_yBlo[(long)T * B * KPAD];
__device__ bf16 d_whh[3][2][H3 * KPAD];
__device__ bf16 d_wih[2][2][H3 * KPAD];

// ---- grid barrier ----
__device__ unsigned int g_arrive = 0;
__device__ volatile unsigned int g_gen = 0;
__device__ __forceinline__ void grid_sync() {
    __syncthreads();
    if (threadIdx.x == 0) {
        __threadfence();
        unsigned int gen = g_gen;
        if (atomicAdd(&g_arrive, 1u) == (unsigned)(NBLK - 1)) {
            g_arrive = 0;
            __threadfence();
            g_gen = gen + 1;
        } else {
            while (g_gen == gen) { }
        }
        __threadfence();
    }
    __syncthreads();
}

// ---- PTX helpers ----
__device__ __forceinline__ u32 s2u(const void* p) {
    u32 a;
    asm("{ .reg .u64 t; cvta.to.shared.u64 t, %1; cvt.u32.u64 %0, t; }" : "=r"(a) : "l"(p));
    return a;
}
#define LDSM_X4(r0, r1, r2, r3, a) \
    asm volatile("ldmatrix.sync.aligned.m8n8.x4.shared.b16 {%0,%1,%2,%3}, [%4];" \
                 : "=r"(r0), "=r"(r1), "=r"(r2), "=r"(r3) : "r"(a))
#define LDSM_X2(r0, r1, a) \
    asm volatile("ldmatrix.sync.aligned.m8n8.x2.shared.b16 {%0,%1}, [%2];" \
                 : "=r"(r0), "=r"(r1) : "r"(a))
#define CP_ASYNC(sdst, gsrc) \
    asm volatile("cp.async.cg.shared.global [%0], [%1], 16;" :: "r"(sdst), "l"(gsrc))
#define CP_COMMIT() asm volatile("cp.async.commit_group;" ::: "memory")
#define CP_WAIT1() asm volatile("cp.async.wait_group 1;" ::: "memory")
#define CP_WAIT0() asm volatile("cp.async.wait_group 0;" ::: "memory")
#define BARWG(wg) asm volatile("bar.sync %0, 256;" :: "r"((wg) + 1) : "memory")

__device__ __forceinline__ void hmma(float c[4], const u32 a[4], u32 b0, u32 b1) {
    asm volatile(
        "mma.sync.aligned.m16n8k16.row.col.f32.bf16.bf16.f32 "
        "{%0,%1,%2,%3}, {%4,%5,%6,%7}, {%8,%9}, {%0,%1,%2,%3};"
        : "+f"(c[0]), "+f"(c[1]), "+f"(c[2]), "+f"(c[3])
        : "r"(a[0]), "r"(a[1]), "r"(a[2]), "r"(a[3]), "r"(b0), "r"(b1));
}

__device__ __forceinline__ float sigm(float x) { return 1.f / (1.f + __expf(-x)); }

// ---- weight hi/lo split precompute ----
__device__ void split_mat(const float* __restrict__ w, bf16* __restrict__ hi,
                          bf16* __restrict__ lo) {
    const long n = (long)H3 * KPAD;
    for (long i = (long)blockIdx.x * NTHR + threadIdx.x; i < n; i += (long)NBLK * NTHR) {
        const int r = (int)(i >> 9);
        const int k = (int)(i & (KPAD - 1));
        const float v = (k < H) ? w[(long)r * H + k] : 0.f;
        const bf16 h = __float2bfloat16(v);
        hi[i] = h;
        lo[i] = __float2bfloat16(v - __bfloat162float(h));
    }
}

// ---- load W hi+lo tile into smem ----
__device__ void load_W(const bf16* __restrict__ whi, const bf16* __restrict__ wlo, int n0) {
    for (int idx = threadIdx.x; idx < 3072; idx += NTHR) {
        const int r = idx >> 6;
        const int seg = idx & 63;
        const int g = r >> 4;
        const int n = n0 + (r & 15);
        uint4 vh = make_uint4(0, 0, 0, 0), vl = vh;
        if (n < H) {
            const long off = (long)(g * H + n) * KPAD + seg * 8;
            vh = *(const uint4*)(whi + off);
            vl = *(const uint4*)(wlo + off);
        }
        const u32 so = (u32)r * WSTRB + seg * 16;
        *(uint4*)(smc + WHI_OFF + so) = vh;
        *(uint4*)(smc + WLO_OFF + so) = vl;
    }
}

// ---- stage one 64x64 A chunk (hi+lo) for one warpgroup ----
__device__ __forceinline__ void stage_chunk(const bf16* __restrict__ ahi,
                                            const bf16* __restrict__ alo,
                                            int m0, int wg, int c, u32 sA, int wtid) {
#pragma unroll
    for (int i = 0; i < 2; i++) {
        const int idx = wtid + i * 256;
        const int row = idx >> 3;
        const int seg = idx & 7;
        const long go = (long)(m0 + row) * KPAD + wg * 256 + c * 64 + seg * 8;
        const u32 so = (u32)row * ASTRB + seg * 16;
        CP_ASYNC(sA + so, ahi + go);
        CP_ASYNC(sA + ABUF_HI + so, alo + go);
    }
}

// ---- 64x48x512 tile, split-K across 2 warpgroups, 3-term bf16 compensation ----
// cf valid in warpgroup 0 after return.
__device__ void run_tile(const bf16* __restrict__ ahi, const bf16* __restrict__ alo,
                         int m0, u32 sb, float cf[3][4]) {
    const int tid = threadIdx.x;
    const int wg = tid >> 8;
    const int wtid = tid & 255;
    const int w = wtid >> 5;
    const int mi = w >> 1;
    const int ns = w & 1;
    const int lane = tid & 31;

#pragma unroll
    for (int g = 0; g < 3; g++)
#pragma unroll
        for (int j = 0; j < 4; j++) cf[g][j] = 0.f;

    const u32 aoff = (u32)(mi * 16 + (lane & 15)) * ASTRB + (lane >> 4) * 16;
    const int gsel = lane >> 4;
    const int khalf = (lane >> 3) & 1;
    const u32 b01off = (u32)(gsel * 16 + ns * 8 + (lane & 7)) * WSTRB + khalf * 16;
    const int l2 = lane & 15;
    const u32 b2off = (u32)(32 + ns * 8 + (l2 & 7)) * WSTRB + (l2 >> 3) * 16;
    const u32 abase = sb + ABUF_OFF + wg * AWG_STRIDE;
    const u32 kwg = wg * 512;   // byte offset of this wg's k-range within a W row

    stage_chunk(ahi, alo, m0, wg, 0, abase, wtid);
    CP_COMMIT();

#pragma unroll 1
    for (int c = 0; c < 4; c++) {
        if (c < 3) {
            stage_chunk(ahi, alo, m0, wg, c + 1, abase + ((c + 1) & 1) * ABUF_SZ, wtid);
            CP_COMMIT();
            CP_WAIT1();
        } else {
            CP_WAIT0();
        }
        BARWG(wg);

        const u32 aH = abase + (c & 1) * ABUF_SZ + aoff;
        const u32 aL = aH + ABUF_HI;
        const u32 co = kwg + c * 128;
        const u32 bH01 = sb + WHI_OFF + b01off + co;
        const u32 bH2 = sb + WHI_OFF + b2off + co;
        const u32 bL01 = sb + WLO_OFF + b01off + co;
        const u32 bL2 = sb + WLO_OFF + b2off + co;

#pragma unroll
        for (int kk = 0; kk < 4; kk++) {
            const u32 ko = kk * 32;
            u32 ah[4], al[4], bh[4], bh2[2], bl[4], bl2[2];
            LDSM_X4(ah[0], ah[1], ah[2], ah[3], aH + ko);
            LDSM_X4(al[0], al[1], al[2], al[3], aL + ko);
            LDSM_X4(bh[0], bh[1], bh[2], bh[3], bH01 + ko);
            LDSM_X2(bh2[0], bh2[1], bH2 + ko);
            LDSM_X4(bl[0], bl[1], bl[2], bl[3], bL01 + ko);
            LDSM_X2(bl2[0], bl2[1], bL2 + ko);
            hmma(cf[0], ah, bh[0], bh[1]);
            hmma(cf[1], ah, bh[2], bh[3]);
            hmma(cf[2], ah, bh2[0], bh2[1]);
            hmma(cf[0], al, bh[0], bh[1]);
            hmma(cf[1], al, bh[2], bh[3]);
            hmma(cf[2], al, bh2[0], bh2[1]);
            hmma(cf[0], ah, bl[0], bl[1]);
            hmma(cf[1], ah, bl[2], bl[3]);
            hmma(cf[2], ah, bl2[0], bl2[1]);
        }
        BARWG(wg);
    }

    // cross-warpgroup reduction: wg1 -> smem -> wg0
    float* red = (float*)(smc + ABUF_OFF);
    __syncthreads();
    if (wg == 1) {
#pragma unroll
        for (int g = 0; g < 3; g++)
#pragma unroll
            for (int j = 0; j < 4; j++) red[wtid * 12 + g * 4 + j] = cf[g][j];
    }
    __syncthreads();
    if (wg == 0) {
#pragma unroll
        for (int g = 0; g < 3; g++)
#pragma unroll
            for (int j = 0; j < 4; j++) cf[g][j] += red[wtid * 12 + g * 4 + j];
    }
    __syncthreads();   // protect red area before next tile's staging
}

// ---- GRU layer scan: h carried in registers (warpgroup 0) ----
__device__ void scan_layer(const float* __restrict__ gsrc, long gstep,
                           const bf16* __restrict__ whi, const bf16* __restrict__ wlo,
                           const float* __restrict__ bhh,
                           bf16* __restrict__ yhi, bf16* __restrict__ ylo, u32 sb) {
    const int m0 = (blockIdx.x >> 5) * 64;
    const int n0 = (blockIdx.x & 31) * 16;
    const int tid = threadIdx.x;
    const bool wg0 = tid < 256;
    const int w = (tid & 255) >> 5;
    const int mi = w >> 1;
    const int ns = w & 1;
    const int lane = tid & 31;
    const int grp = lane >> 2;
    const int tig = lane & 3;

    load_W(whi, wlo, n0);
    __syncthreads();

    const int rows[2] = {m0 + mi * 16 + grp, m0 + mi * 16 + grp + 8};
    const int cols[2] = {n0 + ns * 8 + tig * 2, n0 + ns * 8 + tig * 2 + 1};
    const bool v[2] = {cols[0] < H, cols[1] < H};
    float br[2], bz[2], bn2[2];
#pragma unroll
    for (int j = 0; j < 2; j++) {
        br[j] = v[j] ? bhh[cols[j]] : 0.f;
        bz[j] = v[j] ? bhh[H + cols[j]] : 0.f;
        bn2[j] = v[j] ? bhh[2 * H + cols[j]] : 0.f;
    }
    float hreg[2][2] = {{0.f, 0.f}, {0.f, 0.f}};

    for (int t = 0; t < T; t++) {
        float ga[2][2][3];
        if (wg0) {
            const float* gp = gsrc + (long)t * gstep;
#pragma unroll
            for (int i = 0; i < 2; i++) {
                const float* gr = gp + (long)rows[i] * H3;
#pragma unroll
                for (int j = 0; j < 2; j++) {
                    ga[i][j][0] = v[j] ? gr[cols[j]] : 0.f;
                    ga[i][j][1] = v[j] ? gr[H + cols[j]] : 0.f;
                    ga[i][j][2] = v[j] ? gr[2 * H + cols[j]] : 0.f;
                }
            }
        }

        float cf[3][4];
        if (t > 0) {
            run_tile(yhi + (long)(t - 1) * B * KPAD, ylo + (long)(t - 1) * B * KPAD,
                     m0, sb, cf);
        } else {
#pragma unroll
            for (int g = 0; g < 3; g++)
#pragma unroll
                for (int j = 0; j < 4; j++) cf[g][j] = 0.f;
        }

        if (wg0) {
#pragma unroll
            for (int i = 0; i < 2; i++) {
                const long obase = ((long)t * B + rows[i]) * KPAD;
#pragma unroll
                for (int j = 0; j < 2; j++) {
                    float h = 0.f;
                    if (v[j]) {
                        const int reg = i * 2 + j;
                        const float r = sigm(ga[i][j][0] + cf[0][reg] + br[j]);
                        const float z = sigm(ga[i][j][1] + cf[1][reg] + bz[j]);
                        const float nn = tanhf(ga[i][j][2] + r * (cf[2][reg] + bn2[j]));
                        h = (1.f - z) * nn + z * hreg[i][j];
                    }
                    hreg[i][j] = h;
                    const bf16 hh = __float2bfloat16(h);
                    yhi[obase + cols[j]] = hh;
                    ylo[obase + cols[j]] = __float2bfloat16(h - __bfloat162float(hh));
                }
            }
        }
        grid_sync();
    }
}

// ---- batched input-gate GEMM ----
__device__ void gate_layer(const bf16* __restrict__ yhi, const bf16* __restrict__ ylo,
                           const bf16* __restrict__ whi, const bf16* __restrict__ wlo,
                           const float* __restrict__ bih, float* __restrict__ G, u32 sb) {
    const int n0 = (blockIdx.x & 31) * 16;
    const int mt0 = blockIdx.x >> 5;
    const int tid = threadIdx.x;
    const bool wg0 = tid < 256;
    const int w = (tid & 255) >> 5;
    const int mi = w >> 1;
    const int ns = w & 1;
    const int lane = tid & 31;
    const int grp = lane >> 2;
    const int tig = lane & 3;

    load_W(whi, wlo, n0);
    __syncthreads();

    const int cols[2] = {n0 + ns * 8 + tig * 2, n0 + ns * 8 + tig * 2 + 1};
    const bool v[2] = {cols[0] < H, cols[1] < H};
    float b0[2], b1[2], b2[2];
#pragma unroll
    for (int j = 0; j < 2; j++) {
        b0[j] = v[j] ? bih[cols[j]] : 0.f;
        b1[j] = v[j] ? bih[H + cols[j]] : 0.f;
        b2[j] = v[j] ? bih[2 * H + cols[j]] : 0.f;
    }

    for (int mt = mt0; mt < MT_GATE; mt += 4) {
        const int m0 = mt * 64;
        float cf[3][4];
        run_tile(yhi, ylo, m0, sb, cf);
        if (wg0) {
#pragma unroll
            for (int i = 0; i < 2; i++) {
                const long m = m0 + mi * 16 + grp + i * 8;
                float* gr = G + m * H3;
#pragma unroll
                for (int j = 0; j < 2; j++) {
                    if (v[j]) {
                        const int reg = i * 2 + j;
                        gr[cols[j]] = cf[0][reg] + b0[j];
                        gr[H + cols[j]] = cf[1][reg] + b1[j];
                        gr[2 * H + cols[j]] = cf[2][reg] + b2[j];
                    }
                }
            }
        }
    }
}

// ---- fc2 + permute to (B, O, T) ----
__device__ void fc2_phase(const bf16* __restrict__ yhi, const bf16* __restrict__ ylo,
                          const float* __restrict__ W, const float* __restrict__ bias,
                          float* __restrict__ out) {
    const int wid = threadIdx.x >> 5;   // 0..15
    const int lane = threadIdx.x & 31;
    const int M = T * B;
    float* rows = (float*)smc;          // 16 x 502 floats
    for (int base = blockIdx.x * 16; base < M; base += NBLK * 16) {
        const int row = base + wid;
        if (row < M) {
            for (int k = lane; k < H; k += 32)
                rows[wid * 502 + k] = __bfloat162float(yhi[(long)row * KPAD + k]) +
                                      __bfloat162float(ylo[(long)row * KPAD + k]);
            __syncwarp();
            const int t = row / B;
            const int b = row % B;
            for (int o = lane; o < O; o += 32) {
                float acc = bias[o];
                const float* wr = W + o * H;
                for (int k = 0; k < H; k++) acc += rows[wid * 502 + k] * wr[k];
                out[((long)b * O + o) * T + t] = acc;
            }
            __syncwarp();
        }
    }
}

// ---- persistent mega-kernel ----
__global__ void __launch_bounds__(NTHR, 1) decoder_kernel(
    const float* __restrict__ x,
    const float* __restrict__ fc1_w, const float* __restrict__ fc1_b,
    const float* __restrict__ w_ih0, const float* __restrict__ w_hh0,
    const float* __restrict__ b_ih0, const float* __restrict__ b_hh0,
    const float* __restrict__ w_ih1, const float* __restrict__ w_hh1,
    const float* __restrict__ b_ih1, const float* __restrict__ b_hh1,
    const float* __restrict__ w_ih2, const float* __restrict__ w_hh2,
    const float* __restrict__ b_ih2, const float* __restrict__ b_hh2,
    const float* __restrict__ fc2_w, const float* __restrict__ fc2_b,
    float* __restrict__ out) {
    const int tid = threadIdx.x;
    const u32 sb = s2u(smc);

    split_mat(w_hh0, d_whh[0][0], d_whh[0][1]);
    split_mat(w_hh1, d_whh[1][0], d_whh[1][1]);
    split_mat(w_hh2, d_whh[2][0], d_whh[2][1]);
    split_mat(w_ih1, d_wih[0][0], d_wih[0][1]);
    split_mat(w_ih2, d_wih[1][0], d_wih[1][1]);

    const int gt = blockIdx.x * NTHR + tid;
    const int GT = NBLK * NTHR;
    for (int i = gt; i < B * D; i += GT) {
        const int b = i / D, d = i % D;
        float acc = fc1_b[d];
        for (int k = 0; k < D; k++) acc += x[b * D + k] * fc1_w[d * D + k];
        d_hin[i] = fmaxf(acc, 0.f);
    }
    grid_sync();
    for (int i = gt; i < B * H3; i += GT) {
        const int b = i / H3, j = i % H3;
        float acc = b_ih0[j];
        for (int k = 0; k < D; k++) acc += d_hin[b * D + k] * w_ih0[j * D + k];
        d_g0[i] = acc;
    }
    grid_sync();

    scan_layer(d_g0, 0, d_whh[0][0], d_whh[0][1], b_hh0, d_yAhi, d_yAlo, sb);
    gate_layer(d_yAhi, d_yAlo, d_wih[0][0], d_wih[0][1], b_ih1, d_gbuf, sb);
    grid_sync();
    scan_layer(d_gbuf, (long)B * H3, d_whh[1][0], d_whh[1][1], b_hh1, d_yBhi, d_yBlo, sb);
    gate_layer(d_yBhi, d_yBlo, d_wih[1][0], d_wih[1][1], b_ih2, d_gbuf, sb);
    grid_sync();
    scan_layer(d_gbuf, (long)B * H3, d_whh[2][0], d_whh[2][1], b_hh2, d_yAhi, d_yAlo, sb);

    fc2_phase(d_yAhi, d_yAlo, fc2_w, fc2_b, out);
}

extern "C" void kernel_launch(void* const* d_in, const int* in_sizes, int n_in,
                              void* d_out, int out_size) {
    const float* x     = (const float*)d_in[0];
    const float* fc1_w = (const float*)d_in[1];
    const float* fc1_b = (const float*)d_in[2];
    const float* w_ih0 = (const float*)d_in[3];
    const float* w_hh0 = (const float*)d_in[4];
    const float* b_ih0 = (const float*)d_in[5];
    const float* b_hh0 = (const float*)d_in[6];
    const float* w_ih1 = (const float*)d_in[7];
    const float* w_hh1 = (const float*)d_in[8];
    const float* b_ih1 = (const float*)d_in[9];
    const float* b_hh1 = (const float*)d_in[10];
    const float* w_ih2 = (const float*)d_in[11];
    const float* w_hh2 = (const float*)d_in[12];
    const float* b_ih2 = (const float*)d_in[13];
    const float* b_hh2 = (const float*)d_in[14];
    const float* fc2_w = (const float*)d_in[15];
    const float* fc2_b = (const float*)d_in[16];
    float* out = (float*)d_out;

    cudaFuncSetAttribute(decoder_kernel, cudaFuncAttributeMaxDynamicSharedMemorySize,
                         SMEM_BYTES);
    decoder_kernel<<<NBLK, NTHR, SMEM_BYTES>>>(x, fc1_w, fc1_b,
                                               w_ih0, w_hh0, b_ih0, b_hh0,
                                               w_ih1, w_hh1, b_ih1, b_hh1,
                                               w_ih2, w_hh2, b_ih2, b_hh2,
                                               fc2_w, fc2_b, out);
}